// round 9
// baseline (speedup 1.0000x reference)
#include <cuda_runtime.h>
#include <cuda.h>
#include <math.h>
#include <stdint.h>

// SRBGCN: 2-layer hyperbolic GCN.
// support = adj(16384^2 fp32) @ msg(16384x32) per layer.
// TMA (SW128) 4-stage mbarrier pipeline -> mma.sync tf32 m16n8k8.
// BM=64, 4 warps, grid=256 (2 CTAs/SM) so co-resident CTAs hide each
// other's mbar-wait/compute/sync bubbles and all 148 SMs stream.
// 3 launches: msgT0 (fused M0 build), gemm0 (epilogue: normalize+selu+
// Poincare + M1 build + msg1^T), gemm1 (epilogue writes final output).

constexpr int NN     = 16384;
constexpr int D      = 32;
constexpr int BM     = 64;                // rows per CTA
constexpr int BK     = 64;                // k per stage (2 x 32-col TMA boxes)
constexpr int STAGES = 4;
constexpr int NITER  = NN / BK;           // 256
constexpr int ADJ_CH_B = 32 * BM * 4;     // 8192 B per 32-col adj chunk
constexpr int MSG_CH_B = 32 * 32 * 4;     // 4096 B per 32-col msg chunk
constexpr int STAGE_B  = 2 * ADJ_CH_B + 2 * MSG_CH_B;  // 24576
constexpr int DYN_B    = STAGES * STAGE_B + 1024;      // 99328 (incl. align slack)

// Scratch (static device arrays; no allocation allowed)
__device__ __align__(1024) float g_msgT[D * NN];   // msgT[n][k], k-contiguous

// ---------------------------------------------------------------------------
__device__ __forceinline__ uint32_t smem_u32(const void* p) {
    return (uint32_t)__cvta_generic_to_shared(p);
}
__device__ __forceinline__ void mma_tf32(float* c,
                                         uint32_t a0, uint32_t a1, uint32_t a2, uint32_t a3,
                                         uint32_t b0, uint32_t b1) {
    asm volatile(
        "mma.sync.aligned.m16n8k8.row.col.f32.tf32.tf32.f32 "
        "{%0,%1,%2,%3}, {%4,%5,%6,%7}, {%8,%9}, {%0,%1,%2,%3};"
        : "+f"(c[0]), "+f"(c[1]), "+f"(c[2]), "+f"(c[3])
        : "r"(a0), "r"(a1), "r"(a2), "r"(a3), "r"(b0), "r"(b1));
}
__device__ __forceinline__ float to_tf32_rna(float x) {
    uint32_t r;
    asm("cvt.rna.tf32.f32 %0, %1;" : "=r"(r) : "f"(x));
    return __uint_as_float(r);
}
__device__ __forceinline__ void mbar_init(uint32_t mbar, uint32_t cnt) {
    asm volatile("mbarrier.init.shared.b64 [%0], %1;" :: "r"(mbar), "r"(cnt) : "memory");
}
__device__ __forceinline__ void mbar_expect_tx(uint32_t mbar, uint32_t bytes) {
    asm volatile("mbarrier.arrive.expect_tx.shared.b64 _, [%0], %1;"
                 :: "r"(mbar), "r"(bytes) : "memory");
}
__device__ __forceinline__ void mbar_wait(uint32_t mbar, uint32_t parity) {
    asm volatile(
        "{\n\t.reg .pred P1;\n\t"
        "WAIT_LOOP_%=:\n\t"
        "mbarrier.try_wait.parity.shared.b64 P1, [%0], %1;\n\t"
        "@P1 bra.uni WAIT_DONE_%=;\n\t"
        "bra.uni WAIT_LOOP_%=;\n\t"
        "WAIT_DONE_%=:\n\t}"
        :: "r"(mbar), "r"(parity) : "memory");
}
__device__ __forceinline__ void tma_load_2d(uint32_t smem_dst, const void* map,
                                            int cx, int cy, uint32_t mbar) {
    asm volatile(
        "cp.async.bulk.tensor.2d.shared::cta.global.tile.mbarrier::complete_tx::bytes "
        "[%0], [%1, {%2, %3}], [%4];"
        :: "r"(smem_dst), "l"(map), "r"(cx), "r"(cy), "r"(mbar) : "memory");
}

// ---------------------------------------------------------------------------
// M-matrix element helper.
// ---------------------------------------------------------------------------
__device__ __forceinline__ float lwh_elem(int i, int j, const float* h,
                                          float ch, float sh, float invn) {
    float ni = (i >= 1) ? h[i] * invn : 0.f;
    float nj = (j >= 1) ? h[j] * invn : 0.f;
    if (i == 0 && j == 0) return ch;
    if (i == 0)           return sh * nj;
    if (j == 0)           return sh * ni;
    return ((i == j) ? 1.f : 0.f) - (1.f - ch) * ni * nj;
}

// ---------------------------------------------------------------------------
// Kernel 1: msgT0. Each block (1024 thr) builds M0, computes
// g_msgT[n][k] = (node @ M0)[k][n] for its 32 rows (tf32-rounded).
// ---------------------------------------------------------------------------
__global__ __launch_bounds__(1024)
void msgT0_kernel(const float* __restrict__ node,
                  const float* __restrict__ Ws,
                  const float* __restrict__ Hs) {
    const float* W = Ws;
    const float* h = Hs;

    __shared__ float LWh[32 * 32];
    __shared__ float Ms[32 * 32];
    __shared__ float sc[3];
    __shared__ float xs[32][33];
    __shared__ float ot[32][33];

    const int ty = threadIdx.x >> 5;
    const int tx = threadIdx.x & 31;

    if (threadIdx.x == 0) {
        float ss = 0.f;
        for (int t = 1; t < 32; t++) { float v = h[t]; ss += v * v; }
        sc[0] = coshf(h[0]);
        sc[1] = sinhf(h[0]);
        sc[2] = rsqrtf(ss + 1e-14f);
    }
    const int r0 = blockIdx.x * 32;
    xs[ty][tx] = node[(size_t)(r0 + ty) * D + tx];
    __syncthreads();

    LWh[ty * 32 + tx] = lwh_elem(ty, tx, h, sc[0], sc[1], sc[2]);
    __syncthreads();

    float m;
    if (ty == 0) {
        m = LWh[tx];
    } else {
        m = 0.f;
        for (int k = 1; k < 32; k++)
            m += W[(k - 1) * 31 + (ty - 1)] * LWh[k * 32 + tx];
    }
    Ms[ty * 32 + tx] = m;
    __syncthreads();

    float acc = 0.f;
#pragma unroll
    for (int i = 0; i < 32; i++)
        acc = fmaf(xs[ty][i], Ms[i * 32 + tx], acc);
    ot[tx][ty] = to_tf32_rna(acc);
    __syncthreads();

    g_msgT[(size_t)ty * NN + r0 + tx] = ot[ty][tx];
}

// ---------------------------------------------------------------------------
// Kernel 2: TMA-fed tf32 mma.sync GEMM + fused epilogue. BM=64, 4 warps.
// Warp w owns rows [w*16, w*16+16), all 32 n-cols.
// ---------------------------------------------------------------------------
__global__ __launch_bounds__(128)
void gemm_epi_kernel(const __grid_constant__ CUtensorMap tma_adj,
                     const __grid_constant__ CUtensorMap tma_msg,
                     const float* __restrict__ Ws,
                     const float* __restrict__ Hs,
                     float* __restrict__ outp,
                     int layer) {
    extern __shared__ float dsm[];
    __shared__ alignas(8) uint64_t full_bar[STAGES];
    __shared__ float sc[3];

    const int tid  = threadIdx.x;
    const int lane = tid & 31;
    const int w    = tid >> 5;     // 0..3
    const int g    = lane >> 2;    // 0..7
    const int c    = lane & 3;     // 0..3
    const int row0 = blockIdx.x * BM;

    // 1024-aligned tile base inside dynamic smem
    const uint32_t sb    = smem_u32(dsm);
    const uint32_t base0 = (sb + 1023u) & ~1023u;
    char* tiles = (char*)dsm + (base0 - sb);

    if (tid == 0) {
#pragma unroll
        for (int s = 0; s < STAGES; s++)
            mbar_init(smem_u32(&full_bar[s]), 1u);
    }
    __syncthreads();
    if (tid == 0)
        asm volatile("fence.proxy.async.shared::cta;" ::: "memory");

    // ---- stage issue (single thread) ---------------------------------------
    auto issue_stage = [&](int j) {
        const int  slot = j % STAGES;
        const int  kt   = j * BK;
        const uint32_t mb = smem_u32(&full_bar[slot]);
        const uint32_t db = base0 + (uint32_t)(slot * STAGE_B);
        mbar_expect_tx(mb, (uint32_t)STAGE_B);
        tma_load_2d(db,                             &tma_adj, kt,      row0, mb);
        tma_load_2d(db + ADJ_CH_B,                  &tma_adj, kt + 32, row0, mb);
        tma_load_2d(db + 2 * ADJ_CH_B,              &tma_msg, kt,      0,    mb);
        tma_load_2d(db + 2 * ADJ_CH_B + MSG_CH_B,   &tma_msg, kt + 32, 0,    mb);
    };

    // ---- prologue -----------------------------------------------------------
    if (tid == 0) {
#pragma unroll
        for (int j = 0; j < STAGES - 1; j++) issue_stage(j);
    }

    float acc[4][4];
#pragma unroll
    for (int nt = 0; nt < 4; nt++)
#pragma unroll
        for (int j = 0; j < 4; j++) acc[nt][j] = 0.f;

    const int r0 = w * 16 + g;
    const int r1 = r0 + 8;

    // ---- main loop ------------------------------------------------------------
    for (int it = 0; it < NITER; it++) {
        const int slot = it % STAGES;
        mbar_wait(smem_u32(&full_bar[slot]), (uint32_t)((it / STAGES) & 1));

        const char* stg = tiles + slot * STAGE_B;
#pragma unroll
        for (int ks = 0; ks < 8; ks++) {
            const float* Ah = (const float*)(stg + (ks >> 2) * ADJ_CH_B);
            const float* Bh = (const float*)(stg + 2 * ADJ_CH_B + (ks >> 2) * MSG_CH_B);
            const int u0 = (ks & 3) * 2;

            uint32_t a0 = __float_as_uint(Ah[r0 * 32 + ((u0    ) ^ g) * 4 + c]);
            uint32_t a1 = __float_as_uint(Ah[r1 * 32 + ((u0    ) ^ g) * 4 + c]);
            uint32_t a2 = __float_as_uint(Ah[r0 * 32 + ((u0 + 1) ^ g) * 4 + c]);
            uint32_t a3 = __float_as_uint(Ah[r1 * 32 + ((u0 + 1) ^ g) * 4 + c]);
#pragma unroll
            for (int nt = 0; nt < 4; nt++) {
                const int n = nt * 8 + g;
                uint32_t b0 = __float_as_uint(Bh[n * 32 + ((u0    ) ^ g) * 4 + c]);
                uint32_t b1 = __float_as_uint(Bh[n * 32 + ((u0 + 1) ^ g) * 4 + c]);
                mma_tf32(acc[nt], a0, a1, a2, a3, b0, b1);
            }
        }
        __syncthreads();

        const int nj = it + STAGES - 1;
        if (tid == 0 && nj < NITER) issue_stage(nj);
    }

    // ---- smem layout for epilogue (pipeline memory now free) ------------------
    float* sup  = (float*)tiles;          // 64 x 33
    float* sup2 = sup  + 64 * 33;         // 64 x 33 (msg1 staging)
    float* LWh  = sup2 + 64 * 33;         // 32 x 32
    float* Ms   = LWh  + 1024;            // 32 x 32

#pragma unroll
    for (int nt = 0; nt < 4; nt++) {
        int cb = nt * 8 + 2 * c;
        sup[r0 * 33 + cb]     = acc[nt][0];
        sup[r0 * 33 + cb + 1] = acc[nt][1];
        sup[r1 * 33 + cb]     = acc[nt][2];
        sup[r1 * 33 + cb + 1] = acc[nt][3];
    }

    // ---- layer 0: build M1 (redundant per CTA, trivial cost) ------------------
    if (layer == 0) {
        const float* W1 = Ws + 31 * 31;
        const float* h1 = Hs + 32;
        if (tid == 0) {
            float ss = 0.f;
            for (int t = 1; t < 32; t++) { float v = h1[t]; ss += v * v; }
            sc[0] = coshf(h1[0]);
            sc[1] = sinhf(h1[0]);
            sc[2] = rsqrtf(ss + 1e-14f);
        }
        __syncthreads();
#pragma unroll
        for (int u = 0; u < 8; u++) {
            int idx = u * 128 + tid;
            LWh[idx] = lwh_elem(idx >> 5, idx & 31, h1, sc[0], sc[1], sc[2]);
        }
        __syncthreads();
#pragma unroll
        for (int u = 0; u < 8; u++) {
            int idx = u * 128 + tid;
            int i = idx >> 5, j = idx & 31;
            float m;
            if (i == 0) {
                m = LWh[j];
            } else {
                m = 0.f;
                for (int k = 1; k < 32; k++)
                    m += W1[(k - 1) * 31 + (i - 1)] * LWh[k * 32 + j];
            }
            Ms[idx] = m;
        }
        __syncthreads();
    } else {
        __syncwarp();   // warp-local sup visibility
    }

    // ---- fused epilogue: normalize + selu + Poincare [+ msg1] ------------------
    const float alpha = 1.6732632423543772f;
    const float scale = 1.0507009873554805f;

    for (int r = w * 16; r < w * 16 + 16; r++) {
        float s = sup[r * 33 + lane];

        float tt = s * s;
        float md = (lane == 0) ? -tt : tt;
#pragma unroll
        for (int o = 16; o; o >>= 1) md += __shfl_xor_sync(0xffffffffu, md, o);

        float denom = sqrtf(fmaxf(fabsf(md), 1e-8f));
        float xv    = s / denom;
        float x0    = __shfl_sync(0xffffffffu, xv, 0);

        float p = (lane == 0) ? 0.f : xv / (x0 + 1.f);
        p = (p > 0.f) ? scale * p : scale * alpha * (expf(p) - 1.f);

        float pn = p * p;
#pragma unroll
        for (int o = 16; o; o >>= 1) pn += __shfl_xor_sync(0xffffffffu, pn, o);

        float inv  = 1.f / (1.f - pn);
        float outv = (lane == 0) ? (1.f + pn) * inv : 2.f * p * inv;

        if (layer == 1) {
            outp[(size_t)(row0 + r) * D + lane] = outv;
        } else {
            float a = 0.f;
#pragma unroll
            for (int k = 0; k < 32; k++)
                a = fmaf(__shfl_sync(0xffffffffu, outv, k), Ms[k * 32 + lane], a);
            sup2[r * 33 + lane] = to_tf32_rna(a);
        }
    }

    // ---- layer 0: coalesced transpose write of msg1 into g_msgT ----------------
    if (layer == 0) {
        __syncthreads();
#pragma unroll
        for (int u = 0; u < 16; u++) {
            int idx = u * 128 + tid;       // 0..2047
            int n   = idx >> 6;            // 0..31
            int r   = idx & 63;            // 0..63
            g_msgT[(size_t)n * NN + row0 + r] = sup2[r * 33 + n];
        }
    }
}

// ---------------------------------------------------------------------------
// Host: tensor-map creation via driver entry point (no -lcuda link needed).
// ---------------------------------------------------------------------------
typedef CUresult (*EncodeTiledFn)(
    CUtensorMap*, CUtensorMapDataType, cuuint32_t, void*,
    const cuuint64_t*, const cuuint64_t*, const cuuint32_t*, const cuuint32_t*,
    CUtensorMapInterleave, CUtensorMapSwizzle, CUtensorMapL2promotion,
    CUtensorMapFloatOOBfill);

static void encode_2d(EncodeTiledFn enc, CUtensorMap* map, void* ptr,
                      uint64_t d0, uint64_t d1, uint32_t b0, uint32_t b1) {
    cuuint64_t dims[2]    = {d0, d1};
    cuuint64_t strides[1] = {d0 * 4};
    cuuint32_t box[2]     = {b0, b1};
    cuuint32_t estr[2]    = {1, 1};
    enc(map, CU_TENSOR_MAP_DATA_TYPE_FLOAT32, 2, ptr, dims, strides, box, estr,
        CU_TENSOR_MAP_INTERLEAVE_NONE, CU_TENSOR_MAP_SWIZZLE_128B,
        CU_TENSOR_MAP_L2_PROMOTION_L2_128B, CU_TENSOR_MAP_FLOAT_OOB_FILL_NONE);
}

extern "C" void kernel_launch(void* const* d_in, const int* in_sizes, int n_in,
                              void* d_out, int out_size) {
    const float* node = (const float*)d_in[0];  // 16384 x 32
    const float* adj  = (const float*)d_in[1];  // 16384 x 16384
    const float* Ws   = (const float*)d_in[2];  // 2 x 31 x 31
    const float* Hs   = (const float*)d_in[3];  // 2 x 32
    float* out = (float*)d_out;                 // 16384 x 32

    void* fn = nullptr;
    cudaDriverEntryPointQueryResult qr;
    cudaGetDriverEntryPoint("cuTensorMapEncodeTiled", &fn, cudaEnableDefault, &qr);
    EncodeTiledFn enc = (EncodeTiledFn)fn;

    void* msgT_ptr = nullptr;
    cudaGetSymbolAddress(&msgT_ptr, g_msgT);

    CUtensorMap map_adj, map_msg;
    encode_2d(enc, &map_adj, (void*)adj, NN, NN, 32, BM);   // box {32 cols, 64 rows}
    encode_2d(enc, &map_msg, msgT_ptr,   NN, D,  32, 32);   // box {32 k, 32 n}

    cudaFuncSetAttribute(gemm_epi_kernel,
                         cudaFuncAttributeMaxDynamicSharedMemorySize, DYN_B);

    const int gemm_blocks = NN / BM;   // 256

    msgT0_kernel<<<NN / 32, 1024>>>(node, Ws, Hs);
    gemm_epi_kernel<<<gemm_blocks, 128, DYN_B>>>(map_adj, map_msg, Ws, Hs, nullptr, 0);
    gemm_epi_kernel<<<gemm_blocks, 128, DYN_B>>>(map_adj, map_msg, Ws, Hs, out, 1);
}

// round 10
// speedup vs baseline: 1.0280x; 1.0280x over previous
#include <cuda_runtime.h>
#include <cuda.h>
#include <math.h>
#include <stdint.h>

// SRBGCN: 2-layer hyperbolic GCN.
// support = adj(16384^2 fp32) @ msg(16384x32) per layer.
// TMA (SW128, L2-promo 256B) 5-stage mbarrier pipeline -> mma.sync tf32.
// 3 launches: msgT0 (lean, smem-staged W), gemm0 (epilogue: normalize+selu+
// Poincare + M1 build + msg1^T), gemm1 (epilogue writes final output).

constexpr int NN     = 16384;
constexpr int D      = 32;
constexpr int BM     = 128;               // rows per CTA
constexpr int BK     = 64;                // k per stage (2 x 32-col TMA boxes)
constexpr int STAGES = 5;
constexpr int NITER  = NN / BK;           // 256
constexpr int ADJ_CH_B = 32 * BM * 4;     // 16384 B per 32-col adj chunk
constexpr int MSG_CH_B = 32 * 32 * 4;     // 4096 B per 32-col msg chunk
constexpr int STAGE_B  = 2 * ADJ_CH_B + 2 * MSG_CH_B;  // 40960
constexpr int DYN_B    = STAGES * STAGE_B + 1024;

// Scratch (static device arrays; no allocation allowed)
__device__ __align__(1024) float g_msgT[D * NN];   // msgT[n][k], k-contiguous

// ---------------------------------------------------------------------------
__device__ __forceinline__ uint32_t smem_u32(const void* p) {
    return (uint32_t)__cvta_generic_to_shared(p);
}
__device__ __forceinline__ void mma_tf32(float* c,
                                         uint32_t a0, uint32_t a1, uint32_t a2, uint32_t a3,
                                         uint32_t b0, uint32_t b1) {
    asm volatile(
        "mma.sync.aligned.m16n8k8.row.col.f32.tf32.tf32.f32 "
        "{%0,%1,%2,%3}, {%4,%5,%6,%7}, {%8,%9}, {%0,%1,%2,%3};"
        : "+f"(c[0]), "+f"(c[1]), "+f"(c[2]), "+f"(c[3])
        : "r"(a0), "r"(a1), "r"(a2), "r"(a3), "r"(b0), "r"(b1));
}
__device__ __forceinline__ float to_tf32_rna(float x) {
    uint32_t r;
    asm("cvt.rna.tf32.f32 %0, %1;" : "=r"(r) : "f"(x));
    return __uint_as_float(r);
}
__device__ __forceinline__ void mbar_init(uint32_t mbar, uint32_t cnt) {
    asm volatile("mbarrier.init.shared.b64 [%0], %1;" :: "r"(mbar), "r"(cnt) : "memory");
}
__device__ __forceinline__ void mbar_expect_tx(uint32_t mbar, uint32_t bytes) {
    asm volatile("mbarrier.arrive.expect_tx.shared.b64 _, [%0], %1;"
                 :: "r"(mbar), "r"(bytes) : "memory");
}
__device__ __forceinline__ void mbar_wait(uint32_t mbar, uint32_t parity) {
    asm volatile(
        "{\n\t.reg .pred P1;\n\t"
        "WAIT_LOOP_%=:\n\t"
        "mbarrier.try_wait.parity.shared.b64 P1, [%0], %1;\n\t"
        "@P1 bra.uni WAIT_DONE_%=;\n\t"
        "bra.uni WAIT_LOOP_%=;\n\t"
        "WAIT_DONE_%=:\n\t}"
        :: "r"(mbar), "r"(parity) : "memory");
}
__device__ __forceinline__ void tma_load_2d(uint32_t smem_dst, const void* map,
                                            int cx, int cy, uint32_t mbar) {
    asm volatile(
        "cp.async.bulk.tensor.2d.shared::cta.global.tile.mbarrier::complete_tx::bytes "
        "[%0], [%1, {%2, %3}], [%4];"
        :: "r"(smem_dst), "l"(map), "r"(cx), "r"(cy), "r"(mbar) : "memory");
}

// ---------------------------------------------------------------------------
__device__ __forceinline__ float lwh_elem(int i, int j, const float* h,
                                          float ch, float sh, float invn) {
    float ni = (i >= 1) ? h[i] * invn : 0.f;
    float nj = (j >= 1) ? h[j] * invn : 0.f;
    if (i == 0 && j == 0) return ch;
    if (i == 0)           return sh * nj;
    if (j == 0)           return sh * ni;
    return ((i == j) ? 1.f : 0.f) - (1.f - ch) * ni * nj;
}

// ---------------------------------------------------------------------------
// Kernel 1: msgT0 (lean). 128 blocks x 1024 threads; block handles 128 rows.
// W0 staged in smem; M0 built once per block; coalesced transpose writes.
// ---------------------------------------------------------------------------
__global__ __launch_bounds__(1024)
void msgT0_kernel(const float* __restrict__ node,
                  const float* __restrict__ Ws,
                  const float* __restrict__ Hs) {
    __shared__ float Wsm[961];
    __shared__ float hsm[32];
    __shared__ float sc[3];
    __shared__ float LWh[1024];
    __shared__ float Ms[1024];
    __shared__ float xs[128][33];
    __shared__ float ot[32][129];

    const int tid = threadIdx.x;
    const int r0  = blockIdx.x * 128;

    // stage W0 + h0
    if (tid < 961) Wsm[tid] = Ws[tid];
    if (tid < 32)  hsm[tid] = Hs[tid];
    // load x rows (coalesced float4): 4096 floats = 1024 float4
    {
        int r  = tid >> 3;
        int c4 = tid & 7;
        float4 v = *reinterpret_cast<const float4*>(node + (size_t)(r0 + r) * D + c4 * 4);
        xs[r][c4 * 4 + 0] = v.x;
        xs[r][c4 * 4 + 1] = v.y;
        xs[r][c4 * 4 + 2] = v.z;
        xs[r][c4 * 4 + 3] = v.w;
    }
    __syncthreads();

    if (tid == 0) {
        float ss = 0.f;
        for (int t = 1; t < 32; t++) { float v = hsm[t]; ss += v * v; }
        sc[0] = coshf(hsm[0]);
        sc[1] = sinhf(hsm[0]);
        sc[2] = rsqrtf(ss + 1e-14f);
    }
    __syncthreads();

    LWh[tid] = lwh_elem(tid >> 5, tid & 31, hsm, sc[0], sc[1], sc[2]);
    __syncthreads();

    {
        int i = tid >> 5, j = tid & 31;
        float m;
        if (i == 0) {
            m = LWh[j];
        } else {
            m = 0.f;
#pragma unroll
            for (int k = 1; k < 32; k++)
                m += Wsm[(k - 1) * 31 + (i - 1)] * LWh[k * 32 + j];
        }
        Ms[tid] = m;
    }
    __syncthreads();

    // each thread: 4 consecutive rows, one n column
    {
        const int n  = tid & 31;
        const int rg = tid >> 5;          // 0..31 -> rows rg*4..rg*4+3
#pragma unroll
        for (int rr = 0; rr < 4; rr++) {
            const int r = rg * 4 + rr;
            float acc = 0.f;
#pragma unroll
            for (int k = 0; k < 32; k++)
                acc = fmaf(xs[r][k], Ms[k * 32 + n], acc);
            ot[n][r] = to_tf32_rna(acc);
        }
    }
    __syncthreads();

    // coalesced write: 4096 floats, idx = n*128 + r
#pragma unroll
    for (int u = 0; u < 4; u++) {
        int idx = u * 1024 + tid;
        int n   = idx >> 7;
        int r   = idx & 127;
        g_msgT[(size_t)n * NN + r0 + r] = ot[n][r];
    }
}

// ---------------------------------------------------------------------------
// Kernel 2: TMA-fed tf32 mma.sync GEMM + fused epilogue (R7 config).
// 256 threads = 8 warps; warp w owns rows [w*16, w*16+16), all 32 n-cols.
// ---------------------------------------------------------------------------
__global__ __launch_bounds__(256)
void gemm_epi_kernel(const __grid_constant__ CUtensorMap tma_adj,
                     const __grid_constant__ CUtensorMap tma_msg,
                     const float* __restrict__ Ws,
                     const float* __restrict__ Hs,
                     float* __restrict__ outp,
                     int layer) {
    extern __shared__ float dsm[];
    __shared__ alignas(8) uint64_t full_bar[STAGES];
    __shared__ float sc[3];

    const int tid  = threadIdx.x;
    const int lane = tid & 31;
    const int w    = tid >> 5;     // 0..7
    const int g    = lane >> 2;    // 0..7
    const int c    = lane & 3;     // 0..3
    const int row0 = blockIdx.x * BM;

    const uint32_t sb    = smem_u32(dsm);
    const uint32_t base0 = (sb + 1023u) & ~1023u;
    char* tiles = (char*)dsm + (base0 - sb);

    if (tid == 0) {
#pragma unroll
        for (int s = 0; s < STAGES; s++)
            mbar_init(smem_u32(&full_bar[s]), 1u);
    }
    __syncthreads();
    if (tid == 0)
        asm volatile("fence.proxy.async.shared::cta;" ::: "memory");

    auto issue_stage = [&](int j) {
        const int  slot = j % STAGES;
        const int  kt   = j * BK;
        const uint32_t mb = smem_u32(&full_bar[slot]);
        const uint32_t db = base0 + (uint32_t)(slot * STAGE_B);
        mbar_expect_tx(mb, (uint32_t)STAGE_B);
        tma_load_2d(db,                             &tma_adj, kt,      row0, mb);
        tma_load_2d(db + ADJ_CH_B,                  &tma_adj, kt + 32, row0, mb);
        tma_load_2d(db + 2 * ADJ_CH_B,              &tma_msg, kt,      0,    mb);
        tma_load_2d(db + 2 * ADJ_CH_B + MSG_CH_B,   &tma_msg, kt + 32, 0,    mb);
    };

    if (tid == 0) {
#pragma unroll
        for (int j = 0; j < STAGES - 1; j++) issue_stage(j);
    }

    float acc[4][4];
#pragma unroll
    for (int nt = 0; nt < 4; nt++)
#pragma unroll
        for (int j = 0; j < 4; j++) acc[nt][j] = 0.f;

    const int r0 = w * 16 + g;
    const int r1 = r0 + 8;

    for (int it = 0; it < NITER; it++) {
        const int slot = it % STAGES;
        mbar_wait(smem_u32(&full_bar[slot]), (uint32_t)((it / STAGES) & 1));

        const char* stg = tiles + slot * STAGE_B;
#pragma unroll
        for (int ks = 0; ks < 8; ks++) {
            const float* Ah = (const float*)(stg + (ks >> 2) * ADJ_CH_B);
            const float* Bh = (const float*)(stg + 2 * ADJ_CH_B + (ks >> 2) * MSG_CH_B);
            const int u0 = (ks & 3) * 2;

            uint32_t a0 = __float_as_uint(Ah[r0 * 32 + ((u0    ) ^ g) * 4 + c]);
            uint32_t a1 = __float_as_uint(Ah[r1 * 32 + ((u0    ) ^ g) * 4 + c]);
            uint32_t a2 = __float_as_uint(Ah[r0 * 32 + ((u0 + 1) ^ g) * 4 + c]);
            uint32_t a3 = __float_as_uint(Ah[r1 * 32 + ((u0 + 1) ^ g) * 4 + c]);
#pragma unroll
            for (int nt = 0; nt < 4; nt++) {
                const int n = nt * 8 + g;
                uint32_t b0 = __float_as_uint(Bh[n * 32 + ((u0    ) ^ g) * 4 + c]);
                uint32_t b1 = __float_as_uint(Bh[n * 32 + ((u0 + 1) ^ g) * 4 + c]);
                mma_tf32(acc[nt], a0, a1, a2, a3, b0, b1);
            }
        }
        __syncthreads();

        const int nj = it + STAGES - 1;
        if (tid == 0 && nj < NITER) issue_stage(nj);
    }

    // ---- epilogue smem (pipeline memory now free) ------------------------------
    float* sup  = (float*)tiles;          // 128 x 33
    float* sup2 = sup  + 128 * 33;        // 128 x 33 (msg1 staging / W1 staging)
    float* LWh  = sup2 + 128 * 33;        // 32 x 32
    float* Ms   = LWh  + 1024;            // 32 x 32

#pragma unroll
    for (int nt = 0; nt < 4; nt++) {
        int cb = nt * 8 + 2 * c;
        sup[r0 * 33 + cb]     = acc[nt][0];
        sup[r0 * 33 + cb + 1] = acc[nt][1];
        sup[r1 * 33 + cb]     = acc[nt][2];
        sup[r1 * 33 + cb + 1] = acc[nt][3];
    }

    // ---- layer 0: build M1 (W1 staged in smem first) ---------------------------
    if (layer == 0) {
        const float* W1 = Ws + 31 * 31;
        const float* h1 = Hs + 32;
        float* Wsm = sup2;                 // temporary W1 staging (961 floats)
#pragma unroll
        for (int u = 0; u < 4; u++) {
            int idx = u * 256 + tid;
            if (idx < 961) Wsm[idx] = W1[idx];
        }
        if (tid == 0) {
            float ss = 0.f;
            for (int t = 1; t < 32; t++) { float v = h1[t]; ss += v * v; }
            sc[0] = coshf(h1[0]);
            sc[1] = sinhf(h1[0]);
            sc[2] = rsqrtf(ss + 1e-14f);
        }
        __syncthreads();
#pragma unroll
        for (int u = 0; u < 4; u++) {
            int idx = u * 256 + tid;
            LWh[idx] = lwh_elem(idx >> 5, idx & 31, h1, sc[0], sc[1], sc[2]);
        }
        __syncthreads();
#pragma unroll
        for (int u = 0; u < 4; u++) {
            int idx = u * 256 + tid;
            int i = idx >> 5, j = idx & 31;
            float m;
            if (i == 0) {
                m = LWh[j];
            } else {
                m = 0.f;
#pragma unroll
                for (int k = 1; k < 32; k++)
                    m += Wsm[(k - 1) * 31 + (i - 1)] * LWh[k * 32 + j];
            }
            Ms[idx] = m;
        }
        __syncthreads();
    } else {
        __syncwarp();
    }

    // ---- fused epilogue: normalize + selu + Poincare [+ msg1] ------------------
    const float alpha = 1.6732632423543772f;
    const float scale = 1.0507009873554805f;

    for (int r = w * 16; r < w * 16 + 16; r++) {
        float s = sup[r * 33 + lane];

        float tt = s * s;
        float md = (lane == 0) ? -tt : tt;
#pragma unroll
        for (int o = 16; o; o >>= 1) md += __shfl_xor_sync(0xffffffffu, md, o);

        float denom = sqrtf(fmaxf(fabsf(md), 1e-8f));
        float xv    = s / denom;
        float x0    = __shfl_sync(0xffffffffu, xv, 0);

        float p = (lane == 0) ? 0.f : xv / (x0 + 1.f);
        p = (p > 0.f) ? scale * p : scale * alpha * (expf(p) - 1.f);

        float pn = p * p;
#pragma unroll
        for (int o = 16; o; o >>= 1) pn += __shfl_xor_sync(0xffffffffu, pn, o);

        float inv  = 1.f / (1.f - pn);
        float outv = (lane == 0) ? (1.f + pn) * inv : 2.f * p * inv;

        if (layer == 1) {
            outp[(size_t)(row0 + r) * D + lane] = outv;
        } else {
            float a = 0.f;
#pragma unroll
            for (int k = 0; k < 32; k++)
                a = fmaf(__shfl_sync(0xffffffffu, outv, k), Ms[k * 32 + lane], a);
            sup2[r * 33 + lane] = to_tf32_rna(a);
        }
    }

    // ---- layer 0: coalesced transpose write of msg1 into g_msgT ----------------
    if (layer == 0) {
        __syncthreads();
#pragma unroll
        for (int u = 0; u < 16; u++) {
            int idx = u * 256 + tid;       // 0..4095
            int n   = idx >> 7;            // 0..31
            int r   = idx & 127;           // 0..127
            g_msgT[(size_t)n * NN + row0 + r] = sup2[r * 33 + n];
        }
    }
}

// ---------------------------------------------------------------------------
// Host: tensor-map creation via driver entry point (no -lcuda link needed).
// ---------------------------------------------------------------------------
typedef CUresult (*EncodeTiledFn)(
    CUtensorMap*, CUtensorMapDataType, cuuint32_t, void*,
    const cuuint64_t*, const cuuint64_t*, const cuuint32_t*, const cuuint32_t*,
    CUtensorMapInterleave, CUtensorMapSwizzle, CUtensorMapL2promotion,
    CUtensorMapFloatOOBfill);

static void encode_2d(EncodeTiledFn enc, CUtensorMap* map, void* ptr,
                      uint64_t d0, uint64_t d1, uint32_t b0, uint32_t b1,
                      CUtensorMapL2promotion promo) {
    cuuint64_t dims[2]    = {d0, d1};
    cuuint64_t strides[1] = {d0 * 4};
    cuuint32_t box[2]     = {b0, b1};
    cuuint32_t estr[2]    = {1, 1};
    enc(map, CU_TENSOR_MAP_DATA_TYPE_FLOAT32, 2, ptr, dims, strides, box, estr,
        CU_TENSOR_MAP_INTERLEAVE_NONE, CU_TENSOR_MAP_SWIZZLE_128B,
        promo, CU_TENSOR_MAP_FLOAT_OOB_FILL_NONE);
}

extern "C" void kernel_launch(void* const* d_in, const int* in_sizes, int n_in,
                              void* d_out, int out_size) {
    const float* node = (const float*)d_in[0];  // 16384 x 32
    const float* adj  = (const float*)d_in[1];  // 16384 x 16384
    const float* Ws   = (const float*)d_in[2];  // 2 x 31 x 31
    const float* Hs   = (const float*)d_in[3];  // 2 x 32
    float* out = (float*)d_out;                 // 16384 x 32

    void* fn = nullptr;
    cudaDriverEntryPointQueryResult qr;
    cudaGetDriverEntryPoint("cuTensorMapEncodeTiled", &fn, cudaEnableDefault, &qr);
    EncodeTiledFn enc = (EncodeTiledFn)fn;

    void* msgT_ptr = nullptr;
    cudaGetSymbolAddress(&msgT_ptr, g_msgT);

    CUtensorMap map_adj, map_msg;
    // adj: 256B L2 promotion = free same-row next-k-chunk prefetch
    encode_2d(enc, &map_adj, (void*)adj, NN, NN, 32, BM,
              CU_TENSOR_MAP_L2_PROMOTION_L2_256B);
    encode_2d(enc, &map_msg, msgT_ptr,   NN, D,  32, 32,
              CU_TENSOR_MAP_L2_PROMOTION_L2_128B);

    cudaFuncSetAttribute(gemm_epi_kernel,
                         cudaFuncAttributeMaxDynamicSharedMemorySize, DYN_B);

    const int gemm_blocks = NN / BM;   // 128

    msgT0_kernel<<<NN / 128, 1024>>>(node, Ws, Hs);
    gemm_epi_kernel<<<gemm_blocks, 256, DYN_B>>>(map_adj, map_msg, Ws, Hs, nullptr, 0);
    gemm_epi_kernel<<<gemm_blocks, 256, DYN_B>>>(map_adj, map_msg, Ws, Hs, out, 1);
}